// round 1
// baseline (speedup 1.0000x reference)
#include <cuda_runtime.h>

// Problem constants
#define B   32
#define HH  512
#define WW  512
#define NN  (HH*WW)      // 262144 per row
#define K1  180          // top-k for rv, ri
#define K2  360          // top-2k for rf
#define NTASK 96         // 3 arrays x 32 rows
#define NBINS 1024       // bins for key >= orderKey(2.0f)
#define BIN_BASE 3072u   // (0xC0000000 >> 20)
#define KEY_MIN  0xC0000000u  // orderKey(2.0f)
#define CAP 4096         // candidate buffer capacity per task
#define CHUNKS 32
#define CHUNK (NN/CHUNKS) // 8192

// Scratch (static device globals: allocation-free)
__device__ unsigned            g_hist[NTASK][NBINS];
__device__ int                 g_candCount[NTASK];
__device__ unsigned            g_threshKey[NTASK];
__device__ unsigned long long  g_cand[NTASK][CAP];
__device__ int                 g_topk[NTASK][K2];   // tasks 0..63 use first K1 entries
__device__ float               g_loss[B];

// Monotonic float -> uint mapping (order-preserving)
__device__ __forceinline__ unsigned orderKey(float f) {
    unsigned u = __float_as_uint(f);
    return (u & 0x80000000u) ? ~u : (u | 0x80000000u);
}

// ---------------------------------------------------------------------------
// 0) Zero scratch (graph replays re-run everything)
// ---------------------------------------------------------------------------
__global__ void zeroKernel() {
    int tid = blockIdx.x * blockDim.x + threadIdx.x;
    int total = NTASK * NBINS;
    for (int i = tid; i < total; i += gridDim.x * blockDim.x)
        ((unsigned*)g_hist)[i] = 0;
    if (tid < NTASK) g_candCount[tid] = 0;
}

// ---------------------------------------------------------------------------
// 1) Histogram of top-12 key bits, only for values >= 2.0 (keys >= KEY_MIN)
// ---------------------------------------------------------------------------
__global__ void histKernel(const float* __restrict__ rv,
                           const float* __restrict__ ri,
                           const float* __restrict__ rf) {
    __shared__ unsigned sh[3][NBINS];
    int t = threadIdx.x;
    for (int i = t; i < 3 * NBINS; i += blockDim.x) ((unsigned*)sh)[i] = 0;
    __syncthreads();

    int row = blockIdx.y, chunk = blockIdx.x;
    size_t base = (size_t)row * NN + (size_t)chunk * CHUNK;
    const float* arrs[3] = { rv, ri, rf };

    #pragma unroll
    for (int a = 0; a < 3; a++) {
        const float4* p = (const float4*)(arrs[a] + base);
        for (int i = t; i < CHUNK / 4; i += blockDim.x) {
            float4 v = p[i];
            unsigned k0 = orderKey(v.x), k1 = orderKey(v.y),
                     k2 = orderKey(v.z), k3 = orderKey(v.w);
            if (k0 >= KEY_MIN) atomicAdd(&sh[a][(k0 >> 20) - BIN_BASE], 1u);
            if (k1 >= KEY_MIN) atomicAdd(&sh[a][(k1 >> 20) - BIN_BASE], 1u);
            if (k2 >= KEY_MIN) atomicAdd(&sh[a][(k2 >> 20) - BIN_BASE], 1u);
            if (k3 >= KEY_MIN) atomicAdd(&sh[a][(k3 >> 20) - BIN_BASE], 1u);
        }
    }
    __syncthreads();

    for (int i = t; i < 3 * NBINS; i += blockDim.x) {
        unsigned v = ((unsigned*)sh)[i];
        if (v) {
            int a = i / NBINS, bin = i % NBINS;
            atomicAdd(&g_hist[a * B + row][bin], v);
        }
    }
}

// ---------------------------------------------------------------------------
// 2) Per-task suffix scan from the top bin: find threshold bin for k-th value
// ---------------------------------------------------------------------------
__global__ void scanKernel() {
    int task = threadIdx.x;
    if (task >= NTASK) return;
    unsigned need = (task < 2 * B) ? K1 : K2;
    unsigned acc = 0;
    int bin = 0;
    for (int bI = NBINS - 1; bI >= 0; bI--) {
        acc += g_hist[task][bI];
        if (acc >= need) { bin = bI; break; }
    }
    g_threshKey[task] = (unsigned)(bin + BIN_BASE) << 20;
}

// ---------------------------------------------------------------------------
// 3) Collect candidates: all elements with key >= task threshold
// ---------------------------------------------------------------------------
__global__ void collectKernel(const float* __restrict__ rv,
                              const float* __restrict__ ri,
                              const float* __restrict__ rf) {
    int row = blockIdx.y, chunk = blockIdx.x;
    size_t base = (size_t)row * NN + (size_t)chunk * CHUNK;
    const float* arrs[3] = { rv, ri, rf };

    #pragma unroll
    for (int a = 0; a < 3; a++) {
        int task = a * B + row;
        unsigned tk = g_threshKey[task];
        const float4* p = (const float4*)(arrs[a] + base);
        for (int i = threadIdx.x; i < CHUNK / 4; i += blockDim.x) {
            float4 v = p[i];
            unsigned idx0 = (unsigned)(chunk * CHUNK + i * 4);
            unsigned ks[4] = { orderKey(v.x), orderKey(v.y),
                               orderKey(v.z), orderKey(v.w) };
            #pragma unroll
            for (int c = 0; c < 4; c++) {
                if (ks[c] >= tk) {
                    int pos = atomicAdd(&g_candCount[task], 1);
                    if (pos < CAP)
                        g_cand[task][pos] =
                            ((unsigned long long)ks[c] << 32) | (unsigned)(~(idx0 + c));
                }
            }
        }
    }
}

// ---------------------------------------------------------------------------
// 4) Exact top-k by ranking composites (key desc, index asc — jax tie-break)
// ---------------------------------------------------------------------------
__global__ void selectKernel() {
    __shared__ unsigned long long shc[CAP];
    int task = blockIdx.x;
    int n = min(g_candCount[task], CAP);
    for (int i = threadIdx.x; i < n; i += blockDim.x) shc[i] = g_cand[task][i];
    __syncthreads();
    int need = (task < 2 * B) ? K1 : K2;
    for (int i = threadIdx.x; i < n; i += blockDim.x) {
        unsigned long long me = shc[i];
        int r = 0;
        for (int j = 0; j < n; j++) r += (shc[j] > me);
        if (r < need) g_topk[task][r] = (int)(~(unsigned)me);
    }
}

// ---------------------------------------------------------------------------
// 5) Coverage: dilated rf bitmap in shared, probe rv∪ri union
// ---------------------------------------------------------------------------
__global__ void coverageKernel() {
    __shared__ unsigned bitmap[NN / 32];   // 32 KB: 512x512 bits
    __shared__ int s_rv[K1];
    __shared__ int s_cover, s_denom;

    int b = blockIdx.x, t = threadIdx.x;
    for (int i = t; i < NN / 32; i += blockDim.x) bitmap[i] = 0;
    if (t == 0) { s_cover = 0; s_denom = 0; }
    for (int i = t; i < K1; i += blockDim.x) s_rv[i] = g_topk[0 * B + b][i];
    __syncthreads();

    // Dilate rf top-360 by Chebyshev radius 3 into the bitmap
    if (t < K2) {
        int idx = g_topk[2 * B + b][t];
        int y = idx >> 9, x = idx & 511;
        int lo = max(x - 3, 0), hi = min(x + 3, 511);
        #pragma unroll
        for (int dy = -3; dy <= 3; dy++) {
            int yy = y + dy;
            if (yy < 0 || yy >= HH) continue;
            int wbase = yy << 4;            // 16 words per row
            int w0 = lo >> 5, w1 = hi >> 5;
            if (w0 == w1) {
                unsigned m = ((1u << (hi - lo + 1)) - 1u) << (lo & 31);
                atomicOr(&bitmap[wbase + w0], m);
            } else {
                unsigned m0 = 0xFFFFFFFFu << (lo & 31);
                unsigned m1 = (1u << ((hi & 31) + 1)) - 1u;  // split span: hi&31 <= 5
                atomicOr(&bitmap[wbase + w0], m0);
                atomicOr(&bitmap[wbase + w1], m1);
            }
        }
    }
    __syncthreads();

    // Probe union of rv and (ri minus rv) points
    if (t < K2) {
        int idx;
        bool isSrc;
        if (t < K1) { idx = s_rv[t]; isSrc = true; }
        else {
            idx = g_topk[1 * B + b][t - K1];
            isSrc = true;
            for (int j = 0; j < K1; j++)
                if (s_rv[j] == idx) { isSrc = false; break; }
        }
        if (isSrc) {
            atomicAdd(&s_denom, 1);
            if ((bitmap[idx >> 5] >> (idx & 31)) & 1u) atomicAdd(&s_cover, 1);
        }
    }
    __syncthreads();
    if (t == 0)
        g_loss[b] = 1.0f - (float)s_cover / (float)max(s_denom, 1);
}

// ---------------------------------------------------------------------------
// 6) Mean over batch -> d_out[0]
// ---------------------------------------------------------------------------
__global__ void finalizeKernel(float* __restrict__ out) {
    if (threadIdx.x == 0) {
        float s = 0.0f;
        for (int i = 0; i < B; i++) s += g_loss[i];
        out[0] = s / (float)B;
    }
}

extern "C" void kernel_launch(void* const* d_in, const int* in_sizes, int n_in,
                              void* d_out, int out_size) {
    const float* rv = (const float*)d_in[0];
    const float* ri = (const float*)d_in[1];
    const float* rf = (const float*)d_in[2];

    zeroKernel<<<96, 1024>>>();
    dim3 g(CHUNKS, B);
    histKernel<<<g, 512>>>(rv, ri, rf);
    scanKernel<<<1, 128>>>();
    collectKernel<<<g, 512>>>(rv, ri, rf);
    selectKernel<<<NTASK, 512>>>();
    coverageKernel<<<B, 512>>>();
    finalizeKernel<<<1, 32>>>((float*)d_out);
}

// round 3
// speedup vs baseline: 1.3694x; 1.3694x over previous
#include <cuda_runtime.h>

#define B   32
#define HH  512
#define WW  512
#define NN  (HH*WW)          // 262144 per row
#define K1  180
#define K2  360
#define NTASK 96             // 3 arrays x 32 rows
#define NBINS 1024
#define HIST_BASE 0xC020u    // (orderKey(2.5f) >> 16)
#define KEY_CAND  0xC0200000u // orderKey(2.5f): speculative collect threshold
#define CAP 4096
#define SCAP 2048
#define CH  8                // chunks per (array,row)
#define CHUNKF (NN/CH)       // 32768 floats per block

// Scratch (static device globals: allocation-free, zero at module load)
__device__ unsigned            g_hist[NTASK][NBINS];
__device__ int                 g_candCount[NTASK];
__device__ unsigned long long  g_cand[NTASK][CAP];
__device__ int                 g_topk[NTASK][K2];
__device__ float               g_loss[B];
__device__ int                 g_done;

// Monotonic float -> uint (order-preserving), branchless
__device__ __forceinline__ unsigned orderKey(float f) {
    unsigned u = __float_as_uint(f);
    return u ^ (((unsigned)((int)u >> 31)) | 0x80000000u);
}

// ---------------------------------------------------------------------------
// 1) Fused single pass: collect candidates (key >= 2.5) + fine histogram
// ---------------------------------------------------------------------------
__global__ void __launch_bounds__(512) collectKernel(
        const float* __restrict__ rv,
        const float* __restrict__ ri,
        const float* __restrict__ rf) {
    __shared__ unsigned sh[NBINS];
    int t = threadIdx.x;
    int task = blockIdx.y;                 // 0..95
    int a = task >> 5, row = task & 31;

    for (int i = t; i < NBINS; i += blockDim.x) sh[i] = 0;
    __syncthreads();

    const float* src = (a == 0 ? rv : (a == 1 ? ri : rf))
                       + (size_t)row * NN + (size_t)blockIdx.x * CHUNKF;
    unsigned idxBase = (unsigned)blockIdx.x * CHUNKF;
    const float4* p = (const float4*)src;

    #pragma unroll
    for (int it = 0; it < 4; it++) {
        int i = t + it * 2048;
        float4 v0 = p[i], v1 = p[i + 512], v2 = p[i + 1024], v3 = p[i + 1536];
        const float4 vs[4] = { v0, v1, v2, v3 };
        const int    off[4] = { i, i + 512, i + 1024, i + 1536 };
        #pragma unroll
        for (int q = 0; q < 4; q++) {
            float fx[4] = { vs[q].x, vs[q].y, vs[q].z, vs[q].w };
            #pragma unroll
            for (int c = 0; c < 4; c++) {
                unsigned k = orderKey(fx[c]);
                if (k >= KEY_CAND) {
                    unsigned bin = min((k >> 16) - HIST_BASE, (unsigned)(NBINS - 1));
                    atomicAdd(&sh[bin], 1u);
                    int pos = atomicAdd(&g_candCount[task], 1);
                    if (pos < CAP) {
                        unsigned gi = idxBase + (unsigned)(off[q] * 4 + c);
                        g_cand[task][pos] = ((unsigned long long)k << 32) | (unsigned)(~gi);
                    }
                }
            }
        }
    }
    __syncthreads();
    for (int i = t; i < NBINS; i += blockDim.x) {
        unsigned v = sh[i];
        if (v) atomicAdd(&g_hist[task][i], v);
    }
}

// ---------------------------------------------------------------------------
// 2) Exact top-k per task: suffix-scan hist -> compact -> rank.
//    Fallback: full per-row recompute if speculation failed (never expected).
// ---------------------------------------------------------------------------
__global__ void __launch_bounds__(512) selectKernel(
        const float* __restrict__ rv,
        const float* __restrict__ ri,
        const float* __restrict__ rf) {
    __shared__ unsigned long long sc[SCAP];
    __shared__ unsigned sh[NBINS];
    __shared__ int s_n;
    __shared__ unsigned s_binLo;

    int task = blockIdx.x, t = threadIdx.x;
    int need = (task < 2 * B) ? K1 : K2;
    int cnt = g_candCount[task];
    if (t == 0) s_n = 0;

    bool fb = (cnt < need) || (cnt > CAP);
    if (!fb) {
        for (int i = t; i < NBINS; i += blockDim.x) sh[i] = g_hist[task][i];
        __syncthreads();
        if (t == 0) {
            unsigned acc = 0; int bi = 0;
            for (int i = NBINS - 1; i >= 0; i--) {
                acc += sh[i];
                if (acc >= (unsigned)need) { bi = i; break; }
            }
            s_binLo = ((unsigned)bi + HIST_BASE) << 16;
        }
        __syncthreads();
        unsigned binLo = s_binLo;
        for (int i = t; i < cnt; i += blockDim.x) {
            unsigned long long v = g_cand[task][i];
            if ((unsigned)(v >> 32) >= binLo) {
                int pos = atomicAdd(&s_n, 1);
                if (pos < SCAP) sc[pos] = v;
            }
        }
    } else {
        // exact fallback: recompute this task from scratch
        int a = task >> 5, row = task & 31;
        const float* src = (a == 0 ? rv : (a == 1 ? ri : rf)) + (size_t)row * NN;
        for (int i = t; i < NBINS; i += blockDim.x) sh[i] = 0;
        __syncthreads();
        for (int i = t; i < NN; i += blockDim.x)
            atomicAdd(&sh[orderKey(src[i]) >> 22], 1u);
        __syncthreads();
        if (t == 0) {
            unsigned acc = 0; int bi = 0;
            for (int i = NBINS - 1; i >= 0; i--) {
                acc += sh[i];
                if (acc >= (unsigned)need) { bi = i; break; }
            }
            s_binLo = (unsigned)bi << 22;
        }
        __syncthreads();
        unsigned binLo = s_binLo;
        for (int i = t; i < NN; i += blockDim.x) {
            unsigned k = orderKey(src[i]);
            if (k >= binLo) {
                int pos = atomicAdd(&s_n, 1);
                if (pos < SCAP)
                    sc[pos] = ((unsigned long long)k << 32) | (unsigned)(~(unsigned)i);
            }
        }
    }
    __syncthreads();

    int n2 = min(s_n, SCAP);
    for (int i = t; i < n2; i += blockDim.x) {
        unsigned long long me = sc[i];
        int r = 0;
        for (int j = 0; j < n2; j++) r += (sc[j] > me);
        if (r < need) g_topk[task][r] = (int)(~(unsigned)me);
    }
}

// ---------------------------------------------------------------------------
// 3) Coverage via dilated rf bitmap; last block finalizes + resets scratch
// ---------------------------------------------------------------------------
__global__ void __launch_bounds__(512) coverageKernel(float* __restrict__ out) {
    __shared__ unsigned bitmap[NN / 32];   // 32 KB bitmap 512x512
    __shared__ int s_rv[K1];
    __shared__ int s_cover, s_denom;
    __shared__ bool s_isLast;

    int b = blockIdx.x, t = threadIdx.x;
    for (int i = t; i < NN / 32; i += blockDim.x) bitmap[i] = 0;
    if (t == 0) { s_cover = 0; s_denom = 0; }
    for (int i = t; i < K1; i += blockDim.x) s_rv[i] = g_topk[0 * B + b][i];
    __syncthreads();

    // Dilate rf top-360 by Chebyshev radius 3
    if (t < K2) {
        int idx = g_topk[2 * B + b][t];
        int y = idx >> 9, x = idx & 511;
        int lo = max(x - 3, 0), hi = min(x + 3, 511);
        #pragma unroll
        for (int dy = -3; dy <= 3; dy++) {
            int yy = y + dy;
            if (yy < 0 || yy >= HH) continue;
            int wbase = yy << 4;
            int w0 = lo >> 5, w1 = hi >> 5;
            if (w0 == w1) {
                unsigned m = ((1u << (hi - lo + 1)) - 1u) << (lo & 31);
                atomicOr(&bitmap[wbase + w0], m);
            } else {
                atomicOr(&bitmap[wbase + w0], 0xFFFFFFFFu << (lo & 31));
                atomicOr(&bitmap[wbase + w1], (1u << ((hi & 31) + 1)) - 1u);
            }
        }
    }
    __syncthreads();

    // Probe union of rv and (ri \ rv)
    if (t < K2) {
        int idx; bool isSrc;
        if (t < K1) { idx = s_rv[t]; isSrc = true; }
        else {
            idx = g_topk[1 * B + b][t - K1];
            isSrc = true;
            for (int j = 0; j < K1; j++)
                if (s_rv[j] == idx) { isSrc = false; break; }
        }
        if (isSrc) {
            atomicAdd(&s_denom, 1);
            if ((bitmap[idx >> 5] >> (idx & 31)) & 1u) atomicAdd(&s_cover, 1);
        }
    }
    __syncthreads();
    if (t == 0) {
        g_loss[b] = 1.0f - (float)s_cover / (float)max(s_denom, 1);
        __threadfence();
        s_isLast = (atomicAdd(&g_done, 1) == B - 1);
    }
    __syncthreads();

    if (s_isLast) {
        if (t == 0) {
            volatile float* gl = g_loss;
            float s = 0.0f;
            for (int i = 0; i < B; i++) s += gl[i];
            out[0] = s / (float)B;
            g_done = 0;
        }
        // reset scratch for the next graph replay
        for (int i = t; i < NTASK * NBINS; i += blockDim.x)
            ((unsigned*)g_hist)[i] = 0;
        if (t < NTASK) g_candCount[t] = 0;
    }
}

extern "C" void kernel_launch(void* const* d_in, const int* in_sizes, int n_in,
                              void* d_out, int out_size) {
    const float* rv = (const float*)d_in[0];
    const float* ri = (const float*)d_in[1];
    const float* rf = (const float*)d_in[2];

    collectKernel<<<dim3(CH, NTASK), 512>>>(rv, ri, rf);
    selectKernel<<<NTASK, 512>>>(rv, ri, rf);
    coverageKernel<<<B, 512>>>((float*)d_out);
}

// round 4
// speedup vs baseline: 2.2109x; 1.6145x over previous
#include <cuda_runtime.h>

#define B   32
#define HH  512
#define WW  512
#define NN  (HH*WW)            // 262144 per row
#define K1  180
#define K2  360
#define NTASK 96               // 3 arrays x 32 rows
#define THRESH_F 2.75f
#define CAP  4096
#define SCAP 2048
#define CH   16                // chunks per task
#define CHUNKF (NN/CH)         // 16384 floats per block

// Scratch (static device globals: allocation-free, zeroed at load)
__device__ int                 g_candCount[NTASK];
__device__ unsigned long long  g_cand[NTASK][CAP];
__device__ int                 g_topk[NTASK][K2];
__device__ float               g_loss[B];
__device__ int                 g_done;

// Monotonic float -> uint (order-preserving), branchless
__device__ __forceinline__ unsigned orderKey(float f) {
    unsigned u = __float_as_uint(f);
    return u ^ (((unsigned)((int)u >> 31)) | 0x80000000u);
}

// ---------------------------------------------------------------------------
// 1) Streaming collect: warp-aggregated compaction of values >= 2.75
// ---------------------------------------------------------------------------
__device__ __forceinline__ void emit4(float4 v, unsigned gi0, int task) {
    float m = fmaxf(fmaxf(v.x, v.y), fmaxf(v.z, v.w));
    if (!__any_sync(0xffffffffu, m >= THRESH_F)) return;
    int lane = threadIdx.x & 31;
    float fx[4] = { v.x, v.y, v.z, v.w };
    #pragma unroll
    for (int c = 0; c < 4; c++) {
        bool pred = fx[c] >= THRESH_F;
        unsigned mask = __ballot_sync(0xffffffffu, pred);
        if (mask) {
            int leader = __ffs(mask) - 1;
            int base = 0;
            if (lane == leader)
                base = atomicAdd(&g_candCount[task], __popc(mask));
            base = __shfl_sync(0xffffffffu, base, leader);
            if (pred) {
                int pos = base + __popc(mask & ((1u << lane) - 1u));
                if (pos < CAP)
                    g_cand[task][pos] =
                        ((unsigned long long)orderKey(fx[c]) << 32) |
                        (unsigned)(~(gi0 + c));
            }
        }
    }
}

__global__ void __launch_bounds__(512) collectKernel(
        const float* __restrict__ rv,
        const float* __restrict__ ri,
        const float* __restrict__ rf) {
    int task  = blockIdx.x >> 4;       // 0..95
    int chunk = blockIdx.x & 15;
    int a = task >> 5, row = task & 31;

    const float* src = (a == 0 ? rv : (a == 1 ? ri : rf))
                       + (size_t)row * NN + (size_t)chunk * CHUNKF;
    const float4* p = (const float4*)src;
    unsigned idxBase = (unsigned)chunk * CHUNKF;
    int t = threadIdx.x;

    #pragma unroll
    for (int it = 0; it < 4; it++) {
        int i0 = t + (2 * it) * 512;
        int i1 = t + (2 * it + 1) * 512;
        float4 va = p[i0];
        float4 vb = p[i1];
        emit4(va, idxBase + (unsigned)i0 * 4, task);
        emit4(vb, idxBase + (unsigned)i1 * 4, task);
    }
}

// ---------------------------------------------------------------------------
// 2) Exact top-k per task: rank ~780 composites in shared.
//    Fallback: full per-row recompute (statistically unreachable).
// ---------------------------------------------------------------------------
__global__ void __launch_bounds__(512) selectKernel(
        const float* __restrict__ rv,
        const float* __restrict__ ri,
        const float* __restrict__ rf) {
    __shared__ unsigned long long sc[SCAP];
    __shared__ unsigned sh[1024];
    __shared__ int s_n;
    __shared__ unsigned s_binLo;

    int task = blockIdx.x, t = threadIdx.x;
    int need = (task < 2 * B) ? K1 : K2;
    int cnt = g_candCount[task];
    if (t == 0) s_n = 0;

    int n2;
    if (cnt >= need && cnt <= SCAP) {
        for (int i = t; i < cnt; i += blockDim.x) sc[i] = g_cand[task][i];
        n2 = cnt;
        __syncthreads();
    } else {
        // exact fallback: radix-hist rescan of this task's row
        int a = task >> 5, row = task & 31;
        const float* src = (a == 0 ? rv : (a == 1 ? ri : rf)) + (size_t)row * NN;
        for (int i = t; i < 1024; i += blockDim.x) sh[i] = 0;
        __syncthreads();
        for (int i = t; i < NN; i += blockDim.x)
            atomicAdd(&sh[orderKey(src[i]) >> 22], 1u);
        __syncthreads();
        if (t == 0) {
            unsigned acc = 0; int bi = 0;
            for (int i = 1023; i >= 0; i--) {
                acc += sh[i];
                if (acc >= (unsigned)need) { bi = i; break; }
            }
            s_binLo = (unsigned)bi << 22;
        }
        __syncthreads();
        unsigned binLo = s_binLo;
        for (int i = t; i < NN; i += blockDim.x) {
            unsigned k = orderKey(src[i]);
            if (k >= binLo) {
                int pos = atomicAdd(&s_n, 1);
                if (pos < SCAP)
                    sc[pos] = ((unsigned long long)k << 32) | (unsigned)(~(unsigned)i);
            }
        }
        __syncthreads();
        n2 = min(s_n, SCAP);
    }

    for (int i = t; i < n2; i += blockDim.x) {
        unsigned long long me = sc[i];
        int r = 0;
        #pragma unroll 4
        for (int j = 0; j < n2; j++) r += (sc[j] > me);
        if (r < need) g_topk[task][r] = (int)(~(unsigned)me);
    }
}

// ---------------------------------------------------------------------------
// 3) Coverage via dilated rf bitmap; last block finalizes + resets scratch
// ---------------------------------------------------------------------------
__global__ void __launch_bounds__(512) coverageKernel(float* __restrict__ out) {
    __shared__ unsigned bitmap[NN / 32];   // 32 KB: 512x512 bits
    __shared__ int s_rv[K1];
    __shared__ int s_cover, s_denom;
    __shared__ bool s_isLast;

    int b = blockIdx.x, t = threadIdx.x;
    for (int i = t; i < NN / 32; i += blockDim.x) bitmap[i] = 0;
    if (t == 0) { s_cover = 0; s_denom = 0; }
    for (int i = t; i < K1; i += blockDim.x) s_rv[i] = g_topk[0 * B + b][i];
    __syncthreads();

    // Dilate rf top-360 by Chebyshev radius 3
    if (t < K2) {
        int idx = g_topk[2 * B + b][t];
        int y = idx >> 9, x = idx & 511;
        int lo = max(x - 3, 0), hi = min(x + 3, 511);
        #pragma unroll
        for (int dy = -3; dy <= 3; dy++) {
            int yy = y + dy;
            if (yy < 0 || yy >= HH) continue;
            int wbase = yy << 4;
            int w0 = lo >> 5, w1 = hi >> 5;
            if (w0 == w1) {
                unsigned m = ((1u << (hi - lo + 1)) - 1u) << (lo & 31);
                atomicOr(&bitmap[wbase + w0], m);
            } else {
                atomicOr(&bitmap[wbase + w0], 0xFFFFFFFFu << (lo & 31));
                atomicOr(&bitmap[wbase + w1], (1u << ((hi & 31) + 1)) - 1u);
            }
        }
    }
    __syncthreads();

    // Probe union of rv and (ri \ rv)
    if (t < K2) {
        int idx; bool isSrc;
        if (t < K1) { idx = s_rv[t]; isSrc = true; }
        else {
            idx = g_topk[1 * B + b][t - K1];
            isSrc = true;
            for (int j = 0; j < K1; j++)
                if (s_rv[j] == idx) { isSrc = false; break; }
        }
        if (isSrc) {
            atomicAdd(&s_denom, 1);
            if ((bitmap[idx >> 5] >> (idx & 31)) & 1u) atomicAdd(&s_cover, 1);
        }
    }
    __syncthreads();
    if (t == 0) {
        g_loss[b] = 1.0f - (float)s_cover / (float)max(s_denom, 1);
        __threadfence();
        s_isLast = (atomicAdd(&g_done, 1) == B - 1);
    }
    __syncthreads();

    if (s_isLast) {
        if (t == 0) {
            volatile float* gl = g_loss;
            float s = 0.0f;
            for (int i = 0; i < B; i++) s += gl[i];
            out[0] = s / (float)B;
            g_done = 0;
        }
        // reset candidate counters for the next graph replay
        if (t < NTASK) g_candCount[t] = 0;
    }
}

extern "C" void kernel_launch(void* const* d_in, const int* in_sizes, int n_in,
                              void* d_out, int out_size) {
    const float* rv = (const float*)d_in[0];
    const float* ri = (const float*)d_in[1];
    const float* rf = (const float*)d_in[2];

    collectKernel<<<NTASK * CH, 512>>>(rv, ri, rf);
    selectKernel<<<NTASK, 512>>>(rv, ri, rf);
    coverageKernel<<<B, 512>>>((float*)d_out);
}